// round 11
// baseline (speedup 1.0000x reference)
#include <cuda_runtime.h>
#include <cuda_bf16.h>
#include <cstdint>
#include <cstddef>

// RNN_5188320494079: N=64, T=1024, D=256, H=256, fp32.
// Inputs: x[N,T,D], h0[N,H], Wx[D,H], Wh[H,H], b[H]. Output: [N,T,H].
//
// Kernel 1: Out = x @ Wx + b (packed-f32x2 SGEMM, in-place into d_out).
// Kernel 2: partial-sum-exchange cluster scan, 128 CTAs, cluster(2) = batch n,
//   512 threads. CTA r only ever reads its OWN 128 h rows. Column c = tid>>1:
//   c<128 -> sender (computes partial for the PEER's column c), c>=128 ->
//   finalizer (own column). Row split q = tid&1 (64 rows each), pair-reduced
//   with one shfl_xor. Exchange = single tagged b64 per column per step via
//   plain st.shared::cluster; consumer spins on its own slot (no mbarrier,
//   no arrive storms). One __syncthreads per step.

#define RNN_N 64
#define RNN_T 1024
#define RNN_D 256
#define RNN_H 256
#define HHALF 128

typedef unsigned long long ull;

__device__ __forceinline__ void ffma2(ull& d, ull a, ull b) {
    asm("fma.rn.f32x2 %0, %1, %2, %0;" : "+l"(d) : "l"(a), "l"(b));
}
__device__ __forceinline__ float2 u2f(ull u) {
    float2 f;
    asm("mov.b64 {%0, %1}, %2;" : "=f"(f.x), "=f"(f.y) : "l"(u));
    return f;
}
__device__ __forceinline__ ull f2u(float a, float b) {
    ull u;
    asm("mov.b64 %0, {%1, %2};" : "=l"(u) : "f"(a), "f"(b));
    return u;
}
__device__ __forceinline__ uint32_t smem_u32(const void* p) {
    uint32_t a;
    asm("{ .reg .u64 t; cvta.to.shared.u64 t, %1; cvt.u32.u64 %0, t; }"
        : "=r"(a) : "l"(p));
    return a;
}

// ---------------------------------------------------------------------------
// Kernel 1: smem-tiled SGEMM, BM=128 BN=128 BK=16, 256 thr, f32x2 micro-kernel.
// (unchanged — FFMA2-bound, ~180us)
// ---------------------------------------------------------------------------
__global__ __launch_bounds__(256, 2)
void gemm_xw_kernel(const float* __restrict__ X, const float* __restrict__ Wx,
                    const float* __restrict__ bias, float* __restrict__ Out) {
    __shared__ __align__(16) float2 Asd[16][128];
    __shared__ __align__(16) float  Bs[16][128];

    const int tid = threadIdx.x;
    const int tx = tid & 15;
    const int ty = tid >> 4;
    const int m0 = blockIdx.x * 128;
    const int n0 = blockIdx.y * 128;

    const int a_row = tid >> 2;
    const int a_col = (tid & 3) << 2;
    const int b_row = tid >> 5;
    const int b_col = (tid & 31) << 2;

    ull acc[8][4];
#pragma unroll
    for (int i = 0; i < 8; i++)
#pragma unroll
        for (int j = 0; j < 4; j++) acc[i][j] = 0ull;

    const float* Xa0 = &X[(size_t)(m0 + a_row) * RNN_D + a_col];
    const float* Xa1 = &X[(size_t)(m0 + a_row + 64) * RNN_D + a_col];
    const float* Wb0 = &Wx[(size_t)b_row * RNN_H + n0 + b_col];
    const float* Wb1 = &Wx[(size_t)(b_row + 8) * RNN_H + n0 + b_col];

    for (int k0 = 0; k0 < RNN_D; k0 += 16) {
        float4 av0 = __ldcs(reinterpret_cast<const float4*>(Xa0 + k0));
        float4 av1 = __ldcs(reinterpret_cast<const float4*>(Xa1 + k0));
        float4 bv0 = *reinterpret_cast<const float4*>(Wb0 + (size_t)k0 * RNN_H);
        float4 bv1 = *reinterpret_cast<const float4*>(Wb1 + (size_t)k0 * RNN_H);
        __syncthreads();
        Asd[a_col + 0][a_row] = make_float2(av0.x, av0.x);
        Asd[a_col + 1][a_row] = make_float2(av0.y, av0.y);
        Asd[a_col + 2][a_row] = make_float2(av0.z, av0.z);
        Asd[a_col + 3][a_row] = make_float2(av0.w, av0.w);
        Asd[a_col + 0][a_row + 64] = make_float2(av1.x, av1.x);
        Asd[a_col + 1][a_row + 64] = make_float2(av1.y, av1.y);
        Asd[a_col + 2][a_row + 64] = make_float2(av1.z, av1.z);
        Asd[a_col + 3][a_row + 64] = make_float2(av1.w, av1.w);
        *reinterpret_cast<float4*>(&Bs[b_row][b_col]) = bv0;
        *reinterpret_cast<float4*>(&Bs[b_row + 8][b_col]) = bv1;
        __syncthreads();
#pragma unroll
        for (int k = 0; k < 16; k++) {
            const ulonglong2* ad = reinterpret_cast<const ulonglong2*>(&Asd[k][ty * 8]);
            ulonglong2 aa0 = ad[0], aa1 = ad[1], aa2 = ad[2], aa3 = ad[3];
            const ulonglong2* bd = reinterpret_cast<const ulonglong2*>(&Bs[k][tx * 8]);
            ulonglong2 bb0 = bd[0], bb1 = bd[1];
            ull ap[8] = {aa0.x, aa0.y, aa1.x, aa1.y, aa2.x, aa2.y, aa3.x, aa3.y};
            ull bp[4] = {bb0.x, bb0.y, bb1.x, bb1.y};
#pragma unroll
            for (int i = 0; i < 8; i++) {
                ffma2(acc[i][0], ap[i], bp[0]);
                ffma2(acc[i][1], ap[i], bp[1]);
                ffma2(acc[i][2], ap[i], bp[2]);
                ffma2(acc[i][3], ap[i], bp[3]);
            }
        }
    }

    float4 bb0 = *reinterpret_cast<const float4*>(&bias[n0 + tx * 8]);
    float4 bb1 = *reinterpret_cast<const float4*>(&bias[n0 + tx * 8 + 4]);
    float bb[8] = {bb0.x, bb0.y, bb0.z, bb0.w, bb1.x, bb1.y, bb1.z, bb1.w};
#pragma unroll
    for (int i = 0; i < 8; i++) {
        size_t r = (size_t)(m0 + ty * 8 + i) * RNN_H + n0 + tx * 8;
        float2 v0 = u2f(acc[i][0]), v1 = u2f(acc[i][1]);
        float2 v2 = u2f(acc[i][2]), v3 = u2f(acc[i][3]);
        float4 o0 = make_float4(v0.x + bb[0], v0.y + bb[1], v1.x + bb[2], v1.y + bb[3]);
        float4 o1 = make_float4(v2.x + bb[4], v2.y + bb[5], v3.x + bb[6], v3.y + bb[7]);
        *reinterpret_cast<float4*>(&Out[r]) = o0;
        *reinterpret_cast<float4*>(&Out[r + 4]) = o1;
    }
}

// ---------------------------------------------------------------------------
// Kernel 2: tagged-slot partial-exchange cluster scan (see header).
// Per step t:
//   all 512 thr: p = sum over 64 own h rows (32 FFMA2, Wh in regs);
//                s = pair total via shfl_xor(1).
//   sender (q==0, c<128):   st.shared::cluster {tag=t, s} -> peer slot[t&1][c].
//   finalizer (q==0, c>=128): spin ld.volatile on own slot[t&1][l] until
//                tag==t; z = xw + s + p_peer; h = tanh(z); hbuf[nxt][l] = h;
//                out[t][col] = h.
//   __syncthreads(); cur ^= 1.
// Parity slots + lockstep causality (overwrite of slot p at t+2 is causally
// after peer consumed it at t) make the protocol ABA-safe and deadlock-free.
// ---------------------------------------------------------------------------
__global__ __launch_bounds__(512, 1) __cluster_dims__(2, 1, 1)
void rnn_scan_kernel(const float* __restrict__ h0,
                     const float* __restrict__ Wh,
                     float* Out) {
    __shared__ __align__(16) float hbuf[2][HHALF];   // own h half, 1KB
    __shared__ __align__(16) ull   qbuf[2][HHALF];   // {tag, partial}, 2KB

    const int tid = threadIdx.x;
    uint32_t rank;
    asm("mov.u32 %0, %%cluster_ctarank;" : "=r"(rank));
    const uint32_t peer = rank ^ 1u;
    const int n = blockIdx.x >> 1;
    const int c = tid >> 1;              // 0..255
    const int q = tid & 1;               // row split
    const bool is_sender = (c < HHALF);
    const int l = is_sender ? c : (c - HHALF);
    const int own_base = (int)rank * HHALF;
    const int peer_base = (int)peer * HHALF;
    const int col = is_sender ? (peer_base + l) : (own_base + l);
    const int row0 = q * 64;             // within own half

    // Register-resident Wh slice: 64 rows (own_base+row0 ..) x my col,
    // packed as 32 row-pairs.
    ull wq[32];
#pragma unroll
    for (int k = 0; k < 32; k++) {
        int r = own_base + row0 + 2 * k;
        wq[k] = f2u(__ldg(&Wh[(size_t)r * RNN_H + col]),
                    __ldg(&Wh[(size_t)(r + 1) * RNN_H + col]));
    }

    float* outn = Out + (size_t)n * RNN_T * RNN_H;

    if (tid < HHALF) {
        hbuf[0][tid] = h0[(size_t)n * RNN_H + own_base + tid];
        qbuf[0][tid] = 0xFFFFFFFF00000000ull;   // invalid tag
        qbuf[1][tid] = 0xFFFFFFFF00000000ull;
    }

    // sender: remote slot addresses; finalizer: xw stream + local slot addr
    float xw_cur = 0.f;
    uint32_t rQ0 = 0, rQ1 = 0, lQ0 = 0, lQ1 = 0;
    if (is_sender && q == 0) {
        uint32_t a0 = smem_u32(&qbuf[0][l]);
        uint32_t a1 = smem_u32(&qbuf[1][l]);
        asm("mapa.shared::cluster.u32 %0, %1, %2;" : "=r"(rQ0) : "r"(a0), "r"(peer));
        asm("mapa.shared::cluster.u32 %0, %1, %2;" : "=r"(rQ1) : "r"(a1), "r"(peer));
    } else if (!is_sender && q == 0) {
        xw_cur = __ldcg(&outn[col]);
        lQ0 = smem_u32(&qbuf[0][l]);
        lQ1 = smem_u32(&qbuf[1][l]);
    }
    __syncthreads();
    // h0 + invalid tags visible cluster-wide before any remote store
    asm volatile("barrier.cluster.arrive.aligned;" ::: "memory");
    asm volatile("barrier.cluster.wait.aligned;" ::: "memory");

    int cur = 0;
    for (int t = 0; t < RNN_T; t++) {
        float xw_nxt = 0.f;
        if (!is_sender && q == 0 && t + 1 < RNN_T)
            xw_nxt = __ldcg(&outn[(size_t)(t + 1) * RNN_H + col]);

        // p = sum over my 64 own h rows (32 packed FFMA2)
        const ulonglong2* hp =
            reinterpret_cast<const ulonglong2*>(&hbuf[cur][row0]);
        ull a0 = 0ull, a1 = 0ull;
#pragma unroll
        for (int m = 0; m < 16; m++) {
            ulonglong2 hv = hp[m];       // 4 h values (LDS.128)
            ffma2(a0, hv.x, wq[2 * m]);
            ffma2(a1, hv.y, wq[2 * m + 1]);
        }
        float2 f0 = u2f(a0), f1 = u2f(a1);
        float s = (f0.x + f0.y) + (f1.x + f1.y);
        s += __shfl_xor_sync(0xffffffffu, s, 1);   // full 128-row partial

        if (is_sender) {
            if (q == 0) {
                // ship tagged partial into peer's parity slot (plain remote st)
                ull pkt;
                asm("mov.b64 %0, {%1, %2};" : "=l"(pkt) : "f"(s), "r"((uint32_t)t));
                uint32_t ra = (t & 1) ? rQ1 : rQ0;
                asm volatile("st.shared::cluster.b64 [%0], %1;"
                             :: "r"(ra), "l"(pkt) : "memory");
            }
        } else if (q == 0) {
            // spin on my own slot until this step's tag lands
            uint32_t la = (t & 1) ? lQ1 : lQ0;
            uint32_t tlo, thi;
            do {
                asm volatile("ld.volatile.shared.v2.u32 {%0, %1}, [%2];"
                             : "=r"(tlo), "=r"(thi) : "r"(la) : "memory");
            } while (thi != (uint32_t)t);
            float pp = __uint_as_float(tlo);
            float z = xw_cur + s + pp;
            float e = __expf(2.0f * z);                  // tanh via MUFU
            float hn = 1.0f - __fdividef(2.0f, e + 1.0f);
            hbuf[cur ^ 1][l] = hn;                       // own h half (local)
            __stcs(&outn[(size_t)t * RNN_H + col], hn);  // overwrite xW slot
            xw_cur = xw_nxt;
        }
        __syncthreads();   // h_{t+1} visible to all threads before next step
        cur ^= 1;
    }

    // keep SMEM alive until all remote stores have drained cluster-wide
    asm volatile("barrier.cluster.arrive.aligned;" ::: "memory");
    asm volatile("barrier.cluster.wait.aligned;" ::: "memory");
}

// ---------------------------------------------------------------------------
extern "C" void kernel_launch(void* const* d_in, const int* in_sizes, int n_in,
                              void* d_out, int out_size) {
    const float* x  = (const float*)d_in[0];   // [N,T,D]
    const float* h0 = (const float*)d_in[1];   // [N,H]
    const float* Wx = (const float*)d_in[2];   // [D,H]
    const float* Wh = (const float*)d_in[3];   // [H,H]
    const float* b  = (const float*)d_in[4];   // [H]
    float* out = (float*)d_out;                // [N,T,H]

    (void)in_sizes; (void)n_in; (void)out_size;

    dim3 g1((RNN_N * RNN_T) / 128, RNN_H / 128);
    gemm_xw_kernel<<<g1, 256>>>(x, Wx, b, out);

    rnn_scan_kernel<<<RNN_N * 2, 512>>>(h0, Wh, out);
}

// round 12
// speedup vs baseline: 1.4955x; 1.4955x over previous
#include <cuda_runtime.h>
#include <cuda_bf16.h>
#include <cstdint>
#include <cstddef>

// RNN_5188320494079: N=64, T=1024, D=256, H=256, fp32.
// Inputs: x[N,T,D], h0[N,H], Wx[D,H], Wh[H,H], b[H]. Output: [N,T,H].
//
// Kernel 1: Out = x @ Wx + b (packed-f32x2 SGEMM, in-place into d_out).
// Kernel 2: R7-structure cluster scan (best measured) with tail cuts:
//   - rank-adjusted row mapping: finalize warps are NEVER fabric-blocked
//   - 64 aggregated b64 st.async sends (was 128 b32) -> half the tx storm
//   - transposed partials: finalize reduce = one LDS.128
//   - double-buffered tx barriers (safe phase separation)

#define RNN_N 64
#define RNN_T 1024
#define RNN_D 256
#define RNN_H 256
#define HHALF 128

typedef unsigned long long ull;

__device__ __forceinline__ void ffma2(ull& d, ull a, ull b) {
    asm("fma.rn.f32x2 %0, %1, %2, %0;" : "+l"(d) : "l"(a), "l"(b));
}
__device__ __forceinline__ float2 u2f(ull u) {
    float2 f;
    asm("mov.b64 {%0, %1}, %2;" : "=f"(f.x), "=f"(f.y) : "l"(u));
    return f;
}
__device__ __forceinline__ ull f2u(float a, float b) {
    ull u;
    asm("mov.b64 %0, {%1, %2};" : "=l"(u) : "f"(a), "f"(b));
    return u;
}
__device__ __forceinline__ uint32_t smem_u32(const void* p) {
    uint32_t a;
    asm("{ .reg .u64 t; cvta.to.shared.u64 t, %1; cvt.u32.u64 %0, t; }"
        : "=r"(a) : "l"(p));
    return a;
}
__device__ __forceinline__ void mbar_wait(uint32_t addr, uint32_t parity) {
    asm volatile(
        "{\n\t.reg .pred P;\n\t"
        "WL%=:\n\t"
        "mbarrier.try_wait.parity.acquire.cta.shared::cta.b64 P, [%0], %1, 0x989680;\n\t"
        "@P bra.uni WD%=;\n\t"
        "bra.uni WL%=;\n\t"
        "WD%=:\n\t}"
        :: "r"(addr), "r"(parity) : "memory");
}
__device__ __forceinline__ void mbar_expect(uint32_t addr, uint32_t bytes) {
    asm volatile("mbarrier.arrive.expect_tx.shared::cta.b64 _, [%0], %1;"
                 :: "r"(addr), "r"(bytes) : "memory");
}

// ---------------------------------------------------------------------------
// Kernel 1: smem-tiled SGEMM, BM=128 BN=128 BK=16, 256 thr, f32x2 micro-kernel.
// (unchanged — FFMA2-bound, ~180us)
// ---------------------------------------------------------------------------
__global__ __launch_bounds__(256, 2)
void gemm_xw_kernel(const float* __restrict__ X, const float* __restrict__ Wx,
                    const float* __restrict__ bias, float* __restrict__ Out) {
    __shared__ __align__(16) float2 Asd[16][128];
    __shared__ __align__(16) float  Bs[16][128];

    const int tid = threadIdx.x;
    const int tx = tid & 15;
    const int ty = tid >> 4;
    const int m0 = blockIdx.x * 128;
    const int n0 = blockIdx.y * 128;

    const int a_row = tid >> 2;
    const int a_col = (tid & 3) << 2;
    const int b_row = tid >> 5;
    const int b_col = (tid & 31) << 2;

    ull acc[8][4];
#pragma unroll
    for (int i = 0; i < 8; i++)
#pragma unroll
        for (int j = 0; j < 4; j++) acc[i][j] = 0ull;

    const float* Xa0 = &X[(size_t)(m0 + a_row) * RNN_D + a_col];
    const float* Xa1 = &X[(size_t)(m0 + a_row + 64) * RNN_D + a_col];
    const float* Wb0 = &Wx[(size_t)b_row * RNN_H + n0 + b_col];
    const float* Wb1 = &Wx[(size_t)(b_row + 8) * RNN_H + n0 + b_col];

    for (int k0 = 0; k0 < RNN_D; k0 += 16) {
        float4 av0 = __ldcs(reinterpret_cast<const float4*>(Xa0 + k0));
        float4 av1 = __ldcs(reinterpret_cast<const float4*>(Xa1 + k0));
        float4 bv0 = *reinterpret_cast<const float4*>(Wb0 + (size_t)k0 * RNN_H);
        float4 bv1 = *reinterpret_cast<const float4*>(Wb1 + (size_t)k0 * RNN_H);
        __syncthreads();
        Asd[a_col + 0][a_row] = make_float2(av0.x, av0.x);
        Asd[a_col + 1][a_row] = make_float2(av0.y, av0.y);
        Asd[a_col + 2][a_row] = make_float2(av0.z, av0.z);
        Asd[a_col + 3][a_row] = make_float2(av0.w, av0.w);
        Asd[a_col + 0][a_row + 64] = make_float2(av1.x, av1.x);
        Asd[a_col + 1][a_row + 64] = make_float2(av1.y, av1.y);
        Asd[a_col + 2][a_row + 64] = make_float2(av1.z, av1.z);
        Asd[a_col + 3][a_row + 64] = make_float2(av1.w, av1.w);
        *reinterpret_cast<float4*>(&Bs[b_row][b_col]) = bv0;
        *reinterpret_cast<float4*>(&Bs[b_row + 8][b_col]) = bv1;
        __syncthreads();
#pragma unroll
        for (int k = 0; k < 16; k++) {
            const ulonglong2* ad = reinterpret_cast<const ulonglong2*>(&Asd[k][ty * 8]);
            ulonglong2 aa0 = ad[0], aa1 = ad[1], aa2 = ad[2], aa3 = ad[3];
            const ulonglong2* bd = reinterpret_cast<const ulonglong2*>(&Bs[k][tx * 8]);
            ulonglong2 bb0 = bd[0], bb1 = bd[1];
            ull ap[8] = {aa0.x, aa0.y, aa1.x, aa1.y, aa2.x, aa2.y, aa3.x, aa3.y};
            ull bp[4] = {bb0.x, bb0.y, bb1.x, bb1.y};
#pragma unroll
            for (int i = 0; i < 8; i++) {
                ffma2(acc[i][0], ap[i], bp[0]);
                ffma2(acc[i][1], ap[i], bp[1]);
                ffma2(acc[i][2], ap[i], bp[2]);
                ffma2(acc[i][3], ap[i], bp[3]);
            }
        }
    }

    float4 bb0 = *reinterpret_cast<const float4*>(&bias[n0 + tx * 8]);
    float4 bb1 = *reinterpret_cast<const float4*>(&bias[n0 + tx * 8 + 4]);
    float bb[8] = {bb0.x, bb0.y, bb0.z, bb0.w, bb1.x, bb1.y, bb1.z, bb1.w};
#pragma unroll
    for (int i = 0; i < 8; i++) {
        size_t r = (size_t)(m0 + ty * 8 + i) * RNN_H + n0 + tx * 8;
        float2 v0 = u2f(acc[i][0]), v1 = u2f(acc[i][1]);
        float2 v2 = u2f(acc[i][2]), v3 = u2f(acc[i][3]);
        float4 o0 = make_float4(v0.x + bb[0], v0.y + bb[1], v1.x + bb[2], v1.y + bb[3]);
        float4 o1 = make_float4(v2.x + bb[4], v2.y + bb[5], v3.x + bb[6], v3.y + bb[7]);
        *reinterpret_cast<float4*>(&Out[r]) = o0;
        *reinterpret_cast<float4*>(&Out[r + 4]) = o1;
    }
}

// ---------------------------------------------------------------------------
// Kernel 2: cluster scan. Grid 128 CTAs, cluster(2) = batch n, rank r owns
// output cols [r*128,+128). 512 threads: col = tid&127 (local col),
// q = tid>>7; row block ibase = ((q + 2*rank)&3)*64 -> q=0,1 are ALWAYS the
// CTA's own h rows (finalize warps never fabric-blocked), q=2,3 peer rows.
// Per thread: Wh[64 rows x 1 col] in regs (32 packed pairs). Partials go to
// transposed Ps[col][q]; finalize (tid<128) reduces with one LDS.128, tanh,
// writes h locally, and even lanes ship {h,h_right} as ONE b64 st.async with
// complete_tx to the peer's hbuf + B[(t+1)&1] (64 txs, 512 bytes total).
// ---------------------------------------------------------------------------
__global__ __launch_bounds__(512, 1) __cluster_dims__(2, 1, 1)
void rnn_scan_kernel(const float* __restrict__ h0,
                     const float* __restrict__ Wh,
                     float* Out) {
    __shared__ __align__(16) float hbuf[2][RNN_H];   // full h, 2KB
    __shared__ __align__(16) float Ps[HHALF][4];     // transposed partials, 2KB
    __shared__ __align__(8)  unsigned long long mbars[2]; // B0, B1

    const int tid = threadIdx.x;
    uint32_t rank;
    asm("mov.u32 %0, %%cluster_ctarank;" : "=r"(rank));
    const uint32_t peer = rank ^ 1u;
    const int n = blockIdx.x >> 1;
    const int col = tid & 127;               // local column
    const int q = tid >> 7;                  // 0..3
    const int ibase = ((q + 2 * (int)rank) & 3) * 64;   // q=0,1 -> own rows
    const bool needs_peer = (q >= 2);
    const int gcol = (int)rank * HHALF + col;            // global column

    const uint32_t mbarB0 = smem_u32((const void*)&mbars[0]);
    const uint32_t mbarB1 = smem_u32((const void*)&mbars[1]);

    if (tid == 0) {
        asm volatile("mbarrier.init.shared.b64 [%0], %1;"
                     :: "r"(mbarB0), "r"(1) : "memory");
        asm volatile("mbarrier.init.shared.b64 [%0], %1;"
                     :: "r"(mbarB1), "r"(1) : "memory");
    }

    // Register Wh slice: rows ibase..ibase+63 x col gcol, 32 packed row-pairs.
    ull wq[32];
#pragma unroll
    for (int k = 0; k < 32; k++) {
        int r = ibase + 2 * k;
        wq[k] = f2u(__ldg(&Wh[(size_t)r * RNN_H + gcol]),
                    __ldg(&Wh[(size_t)(r + 1) * RNN_H + gcol]));
    }

    float* outn = Out + (size_t)n * RNN_T * RNN_H;

    if (tid < RNN_H)
        hbuf[0][tid] = h0[(size_t)n * RNN_H + tid];   // full h0

    // finalize-lane state: xw stream + remote addresses (even lanes send)
    float xw_cur = 0.f;
    uint32_t rH0 = 0, rH1 = 0, rmB0 = 0, rmB1 = 0;
    if (tid < HHALF) {
        xw_cur = __ldcg(&outn[gcol]);
        if ((tid & 1) == 0) {
            uint32_t l0 = smem_u32(&hbuf[0][gcol]);   // 8B-aligned (gcol even)
            uint32_t l1 = smem_u32(&hbuf[1][gcol]);
            asm("mapa.shared::cluster.u32 %0, %1, %2;" : "=r"(rH0) : "r"(l0), "r"(peer));
            asm("mapa.shared::cluster.u32 %0, %1, %2;" : "=r"(rH1) : "r"(l1), "r"(peer));
            asm("mapa.shared::cluster.u32 %0, %1, %2;" : "=r"(rmB0) : "r"(mbarB0), "r"(peer));
            asm("mapa.shared::cluster.u32 %0, %1, %2;" : "=r"(rmB1) : "r"(mbarB1), "r"(peer));
        }
    }
    __syncthreads();
    if (tid == 0) {
        mbar_expect(mbarB1, 512u);   // consumed at t=1 (h_1 arrivals)
        mbar_expect(mbarB0, 512u);   // consumed at t=2 (h_2 arrivals)
    }
    // barriers + h0 visible cluster-wide before any remote st.async
    asm volatile("barrier.cluster.arrive.aligned;" ::: "memory");
    asm volatile("barrier.cluster.wait.aligned;" ::: "memory");

    int cur = 0;
    for (int t = 0; t < RNN_T; t++) {
        float xw_nxt = 0.f;
        if (tid < HHALF && t + 1 < RNN_T)
            xw_nxt = __ldcg(&outn[(size_t)(t + 1) * RNN_H + gcol]);

        // peer-row warps wait for this step's peer h half
        if (needs_peer && t > 0) {
            const uint32_t bw = (t & 1) ? mbarB1 : mbarB0;
            mbar_wait(bw, (uint32_t)((t - 1) >> 1) & 1u);
            if (tid == 256 && t + 2 < RNN_T)    // re-arm this barrier for t+2
                mbar_expect(bw, 512u);
        }

        // 32 packed FFMA2 over my 64 rows (broadcast LDS.128 for h)
        const ulonglong2* hp =
            reinterpret_cast<const ulonglong2*>(&hbuf[cur][ibase]);
        ull a0 = 0ull, a1 = 0ull;
#pragma unroll
        for (int m = 0; m < 16; m++) {
            ulonglong2 hv = hp[m];
            ffma2(a0, hv.x, wq[2 * m]);
            ffma2(a1, hv.y, wq[2 * m + 1]);
        }
        float2 f0 = u2f(a0), f1 = u2f(a1);
        Ps[col][q] = (f0.x + f0.y) + (f1.x + f1.y);
        __syncthreads();

        const int nxt = cur ^ 1;
        if (tid < HHALF) {
            float4 v = *reinterpret_cast<const float4*>(&Ps[col][0]); // 1 LDS.128
            float z = xw_cur + ((v.x + v.y) + (v.z + v.w));
            float e = __expf(2.0f * z);                  // tanh via MUFU
            float hn = 1.0f - __fdividef(2.0f, e + 1.0f);
            if (t + 1 < RNN_T) {
                hbuf[nxt][gcol] = hn;                    // local copy
                float hr = __shfl_down_sync(0xffffffffu, hn, 1);
                if ((tid & 1) == 0) {                    // 64 aggregated sends
                    ull pkt = f2u(hn, hr);
                    uint32_t ra = nxt ? rH1 : rH0;
                    uint32_t rb = ((t + 1) & 1) ? rmB1 : rmB0;
                    asm volatile(
                        "st.async.shared::cluster.mbarrier::complete_tx::bytes.b64 [%0], %1, [%2];"
                        :: "r"(ra), "l"(pkt), "r"(rb) : "memory");
                }
            }
            __stcs(&outn[(size_t)t * RNN_H + gcol], hn); // overwrite xW slot
            xw_cur = xw_nxt;
        }
        __syncthreads();   // local h half visible; Ps reusable
        cur ^= 1;
    }

    // keep SMEM alive until all remote traffic has drained cluster-wide
    asm volatile("barrier.cluster.arrive.aligned;" ::: "memory");
    asm volatile("barrier.cluster.wait.aligned;" ::: "memory");
}

// ---------------------------------------------------------------------------
extern "C" void kernel_launch(void* const* d_in, const int* in_sizes, int n_in,
                              void* d_out, int out_size) {
    const float* x  = (const float*)d_in[0];   // [N,T,D]
    const float* h0 = (const float*)d_in[1];   // [N,H]
    const float* Wx = (const float*)d_in[2];   // [D,H]
    const float* Wh = (const float*)d_in[3];   // [H,H]
    const float* b  = (const float*)d_in[4];   // [H]
    float* out = (float*)d_out;                // [N,T,H]

    (void)in_sizes; (void)n_in; (void)out_size;

    dim3 g1((RNN_N * RNN_T) / 128, RNN_H / 128);
    gemm_xw_kernel<<<g1, 256>>>(x, Wx, b, out);

    rnn_scan_kernel<<<RNN_N * 2, 512>>>(h0, Wh, out);
}

// round 13
// speedup vs baseline: 1.4983x; 1.0018x over previous
#include <cuda_runtime.h>
#include <cuda_bf16.h>
#include <cstdint>
#include <cstddef>

// RNN_5188320494079: N=64, T=1024, D=256, H=256, fp32.
// Inputs: x[N,T,D], h0[N,H], Wx[D,H], Wh[H,H], b[H]. Output: [N,T,H].
//
// Kernel 1: Out = x @ Wx + b (packed-f32x2 SGEMM, in-place into d_out).
// Kernel 2: R7-structure cluster scan (best measured) with tail cuts:
//   - rank-adjusted row mapping: finalize warps are NEVER fabric-blocked
//   - 64 aggregated b64 st.async sends (was 128 b32) -> half the tx storm
//   - transposed partials: finalize reduce = one LDS.128
//   - double-buffered tx barriers (safe phase separation)

#define RNN_N 64
#define RNN_T 1024
#define RNN_D 256
#define RNN_H 256
#define HHALF 128

typedef unsigned long long ull;

__device__ __forceinline__ void ffma2(ull& d, ull a, ull b) {
    asm("fma.rn.f32x2 %0, %1, %2, %0;" : "+l"(d) : "l"(a), "l"(b));
}
__device__ __forceinline__ float2 u2f(ull u) {
    float2 f;
    asm("mov.b64 {%0, %1}, %2;" : "=f"(f.x), "=f"(f.y) : "l"(u));
    return f;
}
__device__ __forceinline__ ull f2u(float a, float b) {
    ull u;
    asm("mov.b64 %0, {%1, %2};" : "=l"(u) : "f"(a), "f"(b));
    return u;
}
__device__ __forceinline__ uint32_t smem_u32(const void* p) {
    uint32_t a;
    asm("{ .reg .u64 t; cvta.to.shared.u64 t, %1; cvt.u32.u64 %0, t; }"
        : "=r"(a) : "l"(p));
    return a;
}
__device__ __forceinline__ void mbar_wait(uint32_t addr, uint32_t parity) {
    asm volatile(
        "{\n\t.reg .pred P;\n\t"
        "WL%=:\n\t"
        "mbarrier.try_wait.parity.acquire.cta.shared::cta.b64 P, [%0], %1, 0x989680;\n\t"
        "@P bra.uni WD%=;\n\t"
        "bra.uni WL%=;\n\t"
        "WD%=:\n\t}"
        :: "r"(addr), "r"(parity) : "memory");
}
__device__ __forceinline__ void mbar_expect(uint32_t addr, uint32_t bytes) {
    asm volatile("mbarrier.arrive.expect_tx.shared::cta.b64 _, [%0], %1;"
                 :: "r"(addr), "r"(bytes) : "memory");
}

// ---------------------------------------------------------------------------
// Kernel 1: smem-tiled SGEMM, BM=128 BN=128 BK=16, 256 thr, f32x2 micro-kernel.
// (unchanged — FFMA2-bound, ~180us)
// ---------------------------------------------------------------------------
__global__ __launch_bounds__(256, 2)
void gemm_xw_kernel(const float* __restrict__ X, const float* __restrict__ Wx,
                    const float* __restrict__ bias, float* __restrict__ Out) {
    __shared__ __align__(16) float2 Asd[16][128];
    __shared__ __align__(16) float  Bs[16][128];

    const int tid = threadIdx.x;
    const int tx = tid & 15;
    const int ty = tid >> 4;
    const int m0 = blockIdx.x * 128;
    const int n0 = blockIdx.y * 128;

    const int a_row = tid >> 2;
    const int a_col = (tid & 3) << 2;
    const int b_row = tid >> 5;
    const int b_col = (tid & 31) << 2;

    ull acc[8][4];
#pragma unroll
    for (int i = 0; i < 8; i++)
#pragma unroll
        for (int j = 0; j < 4; j++) acc[i][j] = 0ull;

    const float* Xa0 = &X[(size_t)(m0 + a_row) * RNN_D + a_col];
    const float* Xa1 = &X[(size_t)(m0 + a_row + 64) * RNN_D + a_col];
    const float* Wb0 = &Wx[(size_t)b_row * RNN_H + n0 + b_col];
    const float* Wb1 = &Wx[(size_t)(b_row + 8) * RNN_H + n0 + b_col];

    for (int k0 = 0; k0 < RNN_D; k0 += 16) {
        float4 av0 = __ldcs(reinterpret_cast<const float4*>(Xa0 + k0));
        float4 av1 = __ldcs(reinterpret_cast<const float4*>(Xa1 + k0));
        float4 bv0 = *reinterpret_cast<const float4*>(Wb0 + (size_t)k0 * RNN_H);
        float4 bv1 = *reinterpret_cast<const float4*>(Wb1 + (size_t)k0 * RNN_H);
        __syncthreads();
        Asd[a_col + 0][a_row] = make_float2(av0.x, av0.x);
        Asd[a_col + 1][a_row] = make_float2(av0.y, av0.y);
        Asd[a_col + 2][a_row] = make_float2(av0.z, av0.z);
        Asd[a_col + 3][a_row] = make_float2(av0.w, av0.w);
        Asd[a_col + 0][a_row + 64] = make_float2(av1.x, av1.x);
        Asd[a_col + 1][a_row + 64] = make_float2(av1.y, av1.y);
        Asd[a_col + 2][a_row + 64] = make_float2(av1.z, av1.z);
        Asd[a_col + 3][a_row + 64] = make_float2(av1.w, av1.w);
        *reinterpret_cast<float4*>(&Bs[b_row][b_col]) = bv0;
        *reinterpret_cast<float4*>(&Bs[b_row + 8][b_col]) = bv1;
        __syncthreads();
#pragma unroll
        for (int k = 0; k < 16; k++) {
            const ulonglong2* ad = reinterpret_cast<const ulonglong2*>(&Asd[k][ty * 8]);
            ulonglong2 aa0 = ad[0], aa1 = ad[1], aa2 = ad[2], aa3 = ad[3];
            const ulonglong2* bd = reinterpret_cast<const ulonglong2*>(&Bs[k][tx * 8]);
            ulonglong2 bb0 = bd[0], bb1 = bd[1];
            ull ap[8] = {aa0.x, aa0.y, aa1.x, aa1.y, aa2.x, aa2.y, aa3.x, aa3.y};
            ull bp[4] = {bb0.x, bb0.y, bb1.x, bb1.y};
#pragma unroll
            for (int i = 0; i < 8; i++) {
                ffma2(acc[i][0], ap[i], bp[0]);
                ffma2(acc[i][1], ap[i], bp[1]);
                ffma2(acc[i][2], ap[i], bp[2]);
                ffma2(acc[i][3], ap[i], bp[3]);
            }
        }
    }

    float4 bb0 = *reinterpret_cast<const float4*>(&bias[n0 + tx * 8]);
    float4 bb1 = *reinterpret_cast<const float4*>(&bias[n0 + tx * 8 + 4]);
    float bb[8] = {bb0.x, bb0.y, bb0.z, bb0.w, bb1.x, bb1.y, bb1.z, bb1.w};
#pragma unroll
    for (int i = 0; i < 8; i++) {
        size_t r = (size_t)(m0 + ty * 8 + i) * RNN_H + n0 + tx * 8;
        float2 v0 = u2f(acc[i][0]), v1 = u2f(acc[i][1]);
        float2 v2 = u2f(acc[i][2]), v3 = u2f(acc[i][3]);
        float4 o0 = make_float4(v0.x + bb[0], v0.y + bb[1], v1.x + bb[2], v1.y + bb[3]);
        float4 o1 = make_float4(v2.x + bb[4], v2.y + bb[5], v3.x + bb[6], v3.y + bb[7]);
        *reinterpret_cast<float4*>(&Out[r]) = o0;
        *reinterpret_cast<float4*>(&Out[r + 4]) = o1;
    }
}

// ---------------------------------------------------------------------------
// Kernel 2: cluster scan. Grid 128 CTAs, cluster(2) = batch n, rank r owns
// output cols [r*128,+128). 512 threads: col = tid&127 (local col),
// q = tid>>7; row block ibase = ((q + 2*rank)&3)*64 -> q=0,1 are ALWAYS the
// CTA's own h rows (finalize warps never fabric-blocked), q=2,3 peer rows.
// Per thread: Wh[64 rows x 1 col] in regs (32 packed pairs). Partials go to
// transposed Ps[col][q]; finalize (tid<128) reduces with one LDS.128, tanh,
// writes h locally, and even lanes ship {h,h_right} as ONE b64 st.async with
// complete_tx to the peer's hbuf + B[(t+1)&1] (64 txs, 512 bytes total).
// ---------------------------------------------------------------------------
__global__ __launch_bounds__(512, 1) __cluster_dims__(2, 1, 1)
void rnn_scan_kernel(const float* __restrict__ h0,
                     const float* __restrict__ Wh,
                     float* Out) {
    __shared__ __align__(16) float hbuf[2][RNN_H];   // full h, 2KB
    __shared__ __align__(16) float Ps[HHALF][4];     // transposed partials, 2KB
    __shared__ __align__(8)  unsigned long long mbars[2]; // B0, B1

    const int tid = threadIdx.x;
    uint32_t rank;
    asm("mov.u32 %0, %%cluster_ctarank;" : "=r"(rank));
    const uint32_t peer = rank ^ 1u;
    const int n = blockIdx.x >> 1;
    const int col = tid & 127;               // local column
    const int q = tid >> 7;                  // 0..3
    const int ibase = ((q + 2 * (int)rank) & 3) * 64;   // q=0,1 -> own rows
    const bool needs_peer = (q >= 2);
    const int gcol = (int)rank * HHALF + col;            // global column

    const uint32_t mbarB0 = smem_u32((const void*)&mbars[0]);
    const uint32_t mbarB1 = smem_u32((const void*)&mbars[1]);

    if (tid == 0) {
        asm volatile("mbarrier.init.shared.b64 [%0], %1;"
                     :: "r"(mbarB0), "r"(1) : "memory");
        asm volatile("mbarrier.init.shared.b64 [%0], %1;"
                     :: "r"(mbarB1), "r"(1) : "memory");
    }

    // Register Wh slice: rows ibase..ibase+63 x col gcol, 32 packed row-pairs.
    ull wq[32];
#pragma unroll
    for (int k = 0; k < 32; k++) {
        int r = ibase + 2 * k;
        wq[k] = f2u(__ldg(&Wh[(size_t)r * RNN_H + gcol]),
                    __ldg(&Wh[(size_t)(r + 1) * RNN_H + gcol]));
    }

    float* outn = Out + (size_t)n * RNN_T * RNN_H;

    if (tid < RNN_H)
        hbuf[0][tid] = h0[(size_t)n * RNN_H + tid];   // full h0

    // finalize-lane state: xw stream + remote addresses (even lanes send)
    float xw_cur = 0.f;
    uint32_t rH0 = 0, rH1 = 0, rmB0 = 0, rmB1 = 0;
    if (tid < HHALF) {
        xw_cur = __ldcg(&outn[gcol]);
        if ((tid & 1) == 0) {
            uint32_t l0 = smem_u32(&hbuf[0][gcol]);   // 8B-aligned (gcol even)
            uint32_t l1 = smem_u32(&hbuf[1][gcol]);
            asm("mapa.shared::cluster.u32 %0, %1, %2;" : "=r"(rH0) : "r"(l0), "r"(peer));
            asm("mapa.shared::cluster.u32 %0, %1, %2;" : "=r"(rH1) : "r"(l1), "r"(peer));
            asm("mapa.shared::cluster.u32 %0, %1, %2;" : "=r"(rmB0) : "r"(mbarB0), "r"(peer));
            asm("mapa.shared::cluster.u32 %0, %1, %2;" : "=r"(rmB1) : "r"(mbarB1), "r"(peer));
        }
    }
    __syncthreads();
    if (tid == 0) {
        mbar_expect(mbarB1, 512u);   // consumed at t=1 (h_1 arrivals)
        mbar_expect(mbarB0, 512u);   // consumed at t=2 (h_2 arrivals)
    }
    // barriers + h0 visible cluster-wide before any remote st.async
    asm volatile("barrier.cluster.arrive.aligned;" ::: "memory");
    asm volatile("barrier.cluster.wait.aligned;" ::: "memory");

    int cur = 0;
    for (int t = 0; t < RNN_T; t++) {
        float xw_nxt = 0.f;
        if (tid < HHALF && t + 1 < RNN_T)
            xw_nxt = __ldcg(&outn[(size_t)(t + 1) * RNN_H + gcol]);

        // peer-row warps wait for this step's peer h half
        if (needs_peer && t > 0) {
            const uint32_t bw = (t & 1) ? mbarB1 : mbarB0;
            mbar_wait(bw, (uint32_t)((t - 1) >> 1) & 1u);
            if (tid == 256 && t + 2 < RNN_T)    // re-arm this barrier for t+2
                mbar_expect(bw, 512u);
        }

        // 32 packed FFMA2 over my 64 rows (broadcast LDS.128 for h)
        const ulonglong2* hp =
            reinterpret_cast<const ulonglong2*>(&hbuf[cur][ibase]);
        ull a0 = 0ull, a1 = 0ull;
#pragma unroll
        for (int m = 0; m < 16; m++) {
            ulonglong2 hv = hp[m];
            ffma2(a0, hv.x, wq[2 * m]);
            ffma2(a1, hv.y, wq[2 * m + 1]);
        }
        float2 f0 = u2f(a0), f1 = u2f(a1);
        Ps[col][q] = (f0.x + f0.y) + (f1.x + f1.y);
        __syncthreads();

        const int nxt = cur ^ 1;
        if (tid < HHALF) {
            float4 v = *reinterpret_cast<const float4*>(&Ps[col][0]); // 1 LDS.128
            float z = xw_cur + ((v.x + v.y) + (v.z + v.w));
            float e = __expf(2.0f * z);                  // tanh via MUFU
            float hn = 1.0f - __fdividef(2.0f, e + 1.0f);
            if (t + 1 < RNN_T) {
                hbuf[nxt][gcol] = hn;                    // local copy
                float hr = __shfl_down_sync(0xffffffffu, hn, 1);
                if ((tid & 1) == 0) {                    // 64 aggregated sends
                    ull pkt = f2u(hn, hr);
                    uint32_t ra = nxt ? rH1 : rH0;
                    uint32_t rb = ((t + 1) & 1) ? rmB1 : rmB0;
                    asm volatile(
                        "st.async.shared::cluster.mbarrier::complete_tx::bytes.b64 [%0], %1, [%2];"
                        :: "r"(ra), "l"(pkt), "r"(rb) : "memory");
                }
            }
            __stcs(&outn[(size_t)t * RNN_H + gcol], hn); // overwrite xW slot
            xw_cur = xw_nxt;
        }
        __syncthreads();   // local h half visible; Ps reusable
        cur ^= 1;
    }

    // keep SMEM alive until all remote traffic has drained cluster-wide
    asm volatile("barrier.cluster.arrive.aligned;" ::: "memory");
    asm volatile("barrier.cluster.wait.aligned;" ::: "memory");
}

// ---------------------------------------------------------------------------
extern "C" void kernel_launch(void* const* d_in, const int* in_sizes, int n_in,
                              void* d_out, int out_size) {
    const float* x  = (const float*)d_in[0];   // [N,T,D]
    const float* h0 = (const float*)d_in[1];   // [N,H]
    const float* Wx = (const float*)d_in[2];   // [D,H]
    const float* Wh = (const float*)d_in[3];   // [H,H]
    const float* b  = (const float*)d_in[4];   // [H]
    float* out = (float*)d_out;                // [N,T,H]

    (void)in_sizes; (void)n_in; (void)out_size;

    dim3 g1((RNN_N * RNN_T) / 128, RNN_H / 128);
    gemm_xw_kernel<<<g1, 256>>>(x, Wx, b, out);

    rnn_scan_kernel<<<RNN_N * 2, 512>>>(h0, Wh, out);
}